// round 10
// baseline (speedup 1.0000x reference)
#include <cuda_runtime.h>
#include <cuda_bf16.h>

// ---------------------------------------------------------------------------
// HilbertSerialization: 2M points -> 26-bit Hilbert+batch code -> stable argsort
// OneSweep-style sort: 3 passes (9,9,8 bits), each pass = ONE kernel with
// ticket-ordered decoupled lookback. 6 launches total.
// Output dtype: FLOAT32 (indices as float; all < 2^24, exact).
// All graph-capturable, zero allocations (static __device__ scratch).
// ---------------------------------------------------------------------------

#define HS_MAXN   2000000
#define TILE      4096
#define THREADS   256
#define NWARP     (THREADS / 32)                  // 8
#define IPT       (TILE / THREADS)                // 16
#define MAXBINS   512
#define NBLK_MAX  ((HS_MAXN + TILE - 1) / TILE)   // 489

#define FLAG_AGG    (1u << 30)
#define FLAG_PREFIX (2u << 30)
#define VAL_MASK    ((1u << 30) - 1u)

__device__ unsigned int g_keys[HS_MAXN];
__device__ uint2        g_pairs_a[HS_MAXN];
__device__ uint2        g_pairs_b[HS_MAXN];
__device__ unsigned int g_hist[3][MAXBINS];       // global digit histograms
__device__ unsigned int g_rowbase[3][MAXBINS];    // exclusive-scanned bases
__device__ unsigned int g_status[3][MAXBINS * NBLK_MAX];
__device__ unsigned int g_ticket[3];
__device__ int g_coords64;

// ---------------------------------------------------------------------------
// detect: coords dtype sniff + zero hist/tickets (runs first every replay)
// ---------------------------------------------------------------------------
__global__ void detect_dtype_kernel(const unsigned int* __restrict__ w, int nwords)
{
    __shared__ int ok;
    if (threadIdx.x == 0) ok = 1;
    __syncthreads();
    for (int i = 2 * threadIdx.x + 1; i < nwords; i += 2 * blockDim.x) {
        if (w[i] != 0u) { ok = 0; break; }
    }
    // zero histograms + tickets
    for (int i = threadIdx.x; i < 3 * MAXBINS; i += blockDim.x)
        ((unsigned int*)g_hist)[i] = 0u;
    if (threadIdx.x < 3) g_ticket[threadIdx.x] = 0u;
    __syncthreads();
    if (threadIdx.x == 0) g_coords64 = ok;
}

// ---------------------------------------------------------------------------
// encode: keys + fused 3-digit histograms + zero status arrays
// grid = ntiles blocks of 256 (16 items/thread)
// ---------------------------------------------------------------------------
__global__ void __launch_bounds__(THREADS)
hilbert_encode_kernel(const unsigned int* __restrict__ coords,
                      const unsigned int* __restrict__ ss,
                      const unsigned int* __restrict__ shifts,
                      unsigned int* __restrict__ keys,
                      int n, int ntiles)
{
    __shared__ unsigned int h1[MAXBINS], h2[MAXBINS], h3[MAXBINS];
    for (int i = threadIdx.x; i < MAXBINS; i += THREADS) {
        h1[i] = 0u; h2[i] = 0u; h3[i] = 0u;
    }
    // zero status arrays (grid-stride; total 3*MAXBINS*ntiles entries)
    {
        long long tot = 3LL * MAXBINS * ntiles;
        unsigned int* st = &g_status[0][0];
        for (long long i = (long long)blockIdx.x * THREADS + threadIdx.x;
             i < tot; i += (long long)gridDim.x * THREADS)
            st[i] = 0u;
    }
    __syncthreads();

    int D = 0, H = 0, W = 0;
    if (ss[1] == 0u) { D = (int)ss[0]; H = (int)ss[2]; W = (int)ss[4]; }
    else             { D = (int)ss[0]; H = (int)ss[1]; W = (int)ss[2]; }
    bool sh = (shifts[0] != 0u);
    int sx = sh ? 15 : 0, sy = sh ? 15 : 0, sz = sh ? 4 : 0;
    bool c64 = (g_coords64 != 0);

    int start = blockIdx.x * TILE;
    int end = start + TILE; if (end > n) end = n;
    for (int i = start + threadIdx.x; i < end; i += THREADS) {
        unsigned int b, zc, yc, xc;              // coords row = [b, z, y, x]
        if (c64) {
            const unsigned int* p = coords + (size_t)i * 8;
            b = p[0]; zc = p[2]; yc = p[4]; xc = p[6];
        } else {
            uint4 c = reinterpret_cast<const uint4*>(coords)[i];
            b = c.x; zc = c.y; yc = c.z; xc = c.w;
        }

        unsigned int x = (unsigned int)(((int)xc + sx) % W);
        unsigned int y = (unsigned int)(((int)yc + sy) % H);
        unsigned int z = (unsigned int)(((int)zc + sz) % D);

        unsigned int g0 = x & 0xFFu, g1 = y & 0xFFu, g2 = z & 0xFFu;

        // Axes -> transposed-gray (packed form of the reference bool algo).
        #pragma unroll
        for (int bit = 0; bit < 8; ++bit) {
            unsigned int low = (1u << (7 - bit)) - 1u;
            { unsigned int m = (g0 >> (7 - bit)) & 1u; if (m) g0 ^= low; }
            { unsigned int m = (g1 >> (7 - bit)) & 1u;
              if (m) g0 ^= low;
              else { unsigned int f = (g0 ^ g1) & low; g1 ^= f; g0 ^= f; } }
            { unsigned int m = (g2 >> (7 - bit)) & 1u;
              if (m) g0 ^= low;
              else { unsigned int f = (g0 ^ g2) & low; g2 ^= f; g0 ^= f; } }
        }

        unsigned int h = 0;
        #pragma unroll
        for (int bit = 7; bit >= 0; --bit) {
            h = (h << 3)
              | (((g0 >> bit) & 1u) << 2)
              | (((g1 >> bit) & 1u) << 1)
              |  ((g2 >> bit) & 1u);
        }
        h ^= h >> 16; h ^= h >> 8; h ^= h >> 4; h ^= h >> 2; h ^= h >> 1;

        unsigned int key = h | (b << 24);
        keys[i] = key;
        atomicAdd(&h1[key & 511u], 1u);
        atomicAdd(&h2[(key >> 9) & 511u], 1u);
        atomicAdd(&h3[key >> 18], 1u);
    }
    __syncthreads();
    for (int i = threadIdx.x; i < MAXBINS; i += THREADS) {
        if (h1[i]) atomicAdd(&g_hist[0][i], h1[i]);
        if (h2[i]) atomicAdd(&g_hist[1][i], h2[i]);
        if (h3[i]) atomicAdd(&g_hist[2][i], h3[i]);
    }
}

// ---------------------------------------------------------------------------
// Block exclusive scan (256 threads, 8 warps). ws holds NWARP+1 uints.
// ---------------------------------------------------------------------------
__device__ __forceinline__ unsigned int block_exscan(unsigned int v,
                                                     unsigned int* ws,
                                                     unsigned int* total)
{
    int lane = threadIdx.x & 31, wid = threadIdx.x >> 5;
    unsigned int inc = v;
    #pragma unroll
    for (int o = 1; o < 32; o <<= 1) {
        unsigned int u = __shfl_up_sync(~0u, inc, o);
        if (lane >= o) inc += u;
    }
    __syncthreads();
    if (lane == 31) ws[wid] = inc;
    __syncthreads();
    if (threadIdx.x == 0) {
        unsigned int s = 0;
        #pragma unroll
        for (int i = 0; i < NWARP; ++i) { unsigned int t = ws[i]; ws[i] = s; s += t; }
        ws[NWARP] = s;
    }
    __syncthreads();
    if (total) *total = ws[NWARP];
    return inc - v + ws[wid];
}

// ---------------------------------------------------------------------------
// scan_hist: one block; exclusive scan of the 3 global histograms.
// ---------------------------------------------------------------------------
__global__ void __launch_bounds__(THREADS)
scan_hist_kernel()
{
    __shared__ unsigned int ws[NWARP + 1];
    for (int p = 0; p < 3; ++p) {
        int base = threadIdx.x * 2;
        unsigned int v0 = g_hist[p][base], v1 = g_hist[p][base + 1];
        unsigned int run = block_exscan(v0 + v1, ws, 0);
        g_rowbase[p][base] = run;
        g_rowbase[p][base + 1] = run + v0;
        __syncthreads();
    }
}

// ---------------------------------------------------------------------------
// sweep: one kernel per pass. Ticket-ordered decoupled lookback.
// FIRST=1: input plain keys, val = index. FINAL=1: output float(val).
// ---------------------------------------------------------------------------
template<int SHIFT, int BITS, int FIRST, int FINAL, int PASS>
__global__ void __launch_bounds__(THREADS)
sweep_kernel(const unsigned int* __restrict__ keys_in,
             const uint2* __restrict__ pairs_in,
             uint2* __restrict__ pairs_out,
             float* __restrict__ outf,
             int n, int ntiles)
{
    const int NBINS = 1 << BITS;
    __shared__ unsigned short cnt[NBINS][NWARP];   // [digit][warp]
    __shared__ unsigned int dpref[NBINS];
    __shared__ unsigned int gbase[NBINS];
    __shared__ unsigned int tcs[NBINS];
    __shared__ unsigned int ws[NWARP + 1];
    __shared__ unsigned int tile_s;

    int t = threadIdx.x, lane = t & 31, w = t >> 5;

    if (t == 0) tile_s = atomicAdd(&g_ticket[PASS], 1u);
    unsigned int* cnt32 = (unsigned int*)&cnt[0][0];
    for (int i = t; i < NBINS * (NWARP / 2); i += THREADS) cnt32[i] = 0;
    __syncthreads();
    int tile = (int)tile_s;
    int start = tile * TILE;

    volatile unsigned int* st =
        (volatile unsigned int*)&g_status[PASS][0];

    // Load (key,val) into registers, warp-blocked tile order (coalesced).
    unsigned int k[IPT], v[IPT];
    bool act[IPT];
    #pragma unroll
    for (int q = 0; q < IPT; ++q) {
        int i = w * (32 * IPT) + q * 32 + lane;
        int g = start + i;
        act[q] = (g < n);
        if (act[q]) {
            if (FIRST) { k[q] = keys_in[g]; v[q] = (unsigned int)g; }
            else       { uint2 p = pairs_in[g]; k[q] = p.x; v[q] = p.y; }
        } else { k[q] = 0u; v[q] = 0u; }
    }

    // Phase 1: per-warp histogram (match-aggregated).
    #pragma unroll
    for (int q = 0; q < IPT; ++q) {
        unsigned int amask = __ballot_sync(~0u, act[q]);
        if (act[q]) {
            unsigned int d = (k[q] >> SHIFT) & (NBINS - 1);
            unsigned int peers = __match_any_sync(amask, d);
            if (lane == (__ffs(peers) - 1))
                cnt[d][w] = (unsigned short)(cnt[d][w] + __popc(peers));
        }
    }
    __syncthreads();

    // Publish per-tile aggregates ASAP (one 32-bit word: flag|count).
    for (int d = t; d < NBINS; d += THREADS) {
        unsigned int tc = 0;
        #pragma unroll
        for (int j = 0; j < NWARP; ++j) tc += cnt[d][j];
        tcs[d] = tc;
        st[(size_t)d * ntiles + tile] = FLAG_AGG | tc;
    }
    __syncthreads();

    // Flat exclusive scan of cnt in (digit, warp) order.
    {
        unsigned short* flat = &cnt[0][0];
        const int E = (NBINS * NWARP) / THREADS;   // 16 (BITS=9) / 8 (BITS=8)
        unsigned int loc[16], s = 0;
        #pragma unroll
        for (int j = 0; j < E; ++j) { loc[j] = flat[t * E + j]; s += loc[j]; }
        unsigned int run = block_exscan(s, ws, 0);
        #pragma unroll
        for (int j = 0; j < E; ++j) {
            flat[t * E + j] = (unsigned short)run;
            run += loc[j];
        }
    }
    __syncthreads();
    for (int d = t; d < NBINS; d += THREADS) dpref[d] = cnt[d][0];

    // Decoupled lookback: one digit per thread (strided).
    for (int d = t; d < NBINS; d += THREADS) {
        unsigned int acc = 0;
        int tt = tile - 1;
        while (tt >= 0) {
            unsigned int s;
            do { s = st[(size_t)d * ntiles + tt]; } while (s == 0u);
            acc += s & VAL_MASK;
            if (s & FLAG_PREFIX) break;
            --tt;
        }
        gbase[d] = g_rowbase[PASS][d] + acc;
        st[(size_t)d * ntiles + tile] = FLAG_PREFIX | (acc + tcs[d]);
    }
    __syncthreads();

    // Phase 2: stable rank -> direct scattered write.
    #pragma unroll
    for (int q = 0; q < IPT; ++q) {
        unsigned int amask = __ballot_sync(~0u, act[q]);
        if (act[q]) {
            unsigned int d = (k[q] >> SHIFT) & (NBINS - 1);
            unsigned int peers = __match_any_sync(amask, d);
            int leader = __ffs(peers) - 1;
            unsigned int base = 0;
            if (lane == leader) {
                base = cnt[d][w];
                cnt[d][w] = (unsigned short)(base + __popc(peers));
            }
            base = __shfl_sync(peers, base, leader);
            unsigned int rank = base + __popc(peers & ((1u << lane) - 1u));
            unsigned int pos = gbase[d] + rank - dpref[d];
            if (FINAL) outf[pos] = (float)v[q];
            else       pairs_out[pos] = make_uint2(k[q], v[q]);
        }
    }
}

// ---------------------------------------------------------------------------
// Host
// ---------------------------------------------------------------------------
extern "C" void kernel_launch(void* const* d_in, const int* in_sizes, int n_in,
                              void* d_out, int out_size)
{
    // Identify inputs by size signature.
    int ci = 0;
    for (int i = 1; i < n_in; ++i)
        if (in_sizes[i] > in_sizes[ci]) ci = i;
    int si = -1, hi = -1;
    for (int i = 0; i < n_in; ++i) {
        if (i == ci) continue;
        if (si < 0) { si = i; continue; }
        if (hi < 0) { hi = i; continue; }
    }
    if (hi >= 0 && in_sizes[hi] > in_sizes[si]) { int tq = si; si = hi; hi = tq; }
    if (si < 0) si = ci;
    if (hi < 0) hi = si;

    const unsigned int* coords = (const unsigned int*)d_in[ci];
    const unsigned int* ss     = (const unsigned int*)d_in[si];
    const unsigned int* shifts = (const unsigned int*)d_in[hi];

    int n = out_size;
    if (n > HS_MAXN) n = HS_MAXN;
    if (n <= 0) return;

    unsigned int* ka;
    uint2 *pa, *pb;
    cudaGetSymbolAddress((void**)&ka, g_keys);
    cudaGetSymbolAddress((void**)&pa, g_pairs_a);
    cudaGetSymbolAddress((void**)&pb, g_pairs_b);

    int ntiles = (n + TILE - 1) / TILE;

    detect_dtype_kernel<<<1, 256>>>(coords, 4096);
    hilbert_encode_kernel<<<ntiles, THREADS>>>(coords, ss, shifts, ka, n, ntiles);
    scan_hist_kernel<<<1, THREADS>>>();

    sweep_kernel<0, 9, 1, 0, 0><<<ntiles, THREADS>>>(
        ka, 0, pb, 0, n, ntiles);
    sweep_kernel<9, 9, 0, 0, 1><<<ntiles, THREADS>>>(
        0, pb, pa, 0, n, ntiles);
    sweep_kernel<18, 8, 0, 1, 2><<<ntiles, THREADS>>>(
        0, pa, 0, (float*)d_out, n, ntiles);
}

// round 12
// speedup vs baseline: 1.8244x; 1.8244x over previous
#include <cuda_runtime.h>
#include <cuda_bf16.h>

// ---------------------------------------------------------------------------
// HilbertSerialization: 2M points -> 26-bit Hilbert+batch code -> stable argsort
// Output dtype: FLOAT32 (indices as float; all < 2^24, exact).
// 3-pass stable LSD radix sort (9,9,8 bits). Histograms are FUSED into the
// producing kernel (encode -> pass1 counts; scatter_p -> pass_{p+1} counts via
// pos/TILE atomics). Scatter uses a single match pass for stable ranking.
// 11 launches. All graph-capturable, zero allocations.
// ---------------------------------------------------------------------------

#define HS_MAXN   2000000
#define TILE      4096
#define TILE_LOG  12
#define THREADS   256
#define NWARP     (THREADS / 32)                  // 8
#define IPT       (TILE / THREADS)                // 16
#define MAXBINS   512
#define NBLK_MAX  ((HS_MAXN + TILE - 1) / TILE)   // 489

__device__ unsigned int g_keys[HS_MAXN];
__device__ uint2        g_pairs_a[HS_MAXN];
__device__ uint2        g_pairs_b[HS_MAXN];
__device__ unsigned int g_cnt[3][MAXBINS * NBLK_MAX];  // per-pass [digit][tile]
__device__ unsigned int g_rowtot[MAXBINS];
__device__ unsigned int g_rowbase[MAXBINS];
__device__ int g_coords64;

// ---------------------------------------------------------------------------
__global__ void detect_dtype_kernel(const unsigned int* __restrict__ w, int nwords)
{
    __shared__ int ok;
    if (threadIdx.x == 0) ok = 1;
    __syncthreads();
    for (int i = 2 * threadIdx.x + 1; i < nwords; i += 2 * blockDim.x) {
        if (w[i] != 0u) { ok = 0; break; }
    }
    __syncthreads();
    if (threadIdx.x == 0) g_coords64 = ok;
}

// ---------------------------------------------------------------------------
// encode: keys + pass-1 per-tile counts (smem hist) + zero pass-2/3 counts.
// ---------------------------------------------------------------------------
__global__ void __launch_bounds__(THREADS)
hilbert_encode_kernel(const unsigned int* __restrict__ coords,
                      const unsigned int* __restrict__ ss,
                      const unsigned int* __restrict__ shifts,
                      unsigned int* __restrict__ keys,
                      int n, int ntiles)
{
    __shared__ unsigned int h1[MAXBINS];
    for (int i = threadIdx.x; i < MAXBINS; i += THREADS) h1[i] = 0u;
    // zero pass-2/3 counts (must precede scatter1/scatter2 atomics; kernel
    // ordering guarantees it)
    {
        long long tot = 2LL * MAXBINS * ntiles;
        unsigned int* st = &g_cnt[1][0];
        for (long long i = (long long)blockIdx.x * THREADS + threadIdx.x;
             i < tot; i += (long long)gridDim.x * THREADS)
            st[i] = 0u;
    }
    __syncthreads();

    int D, H, W;                                  // sparse_shape = [D, H, W]
    if (ss[1] == 0u) { D = (int)ss[0]; H = (int)ss[2]; W = (int)ss[4]; }
    else             { D = (int)ss[0]; H = (int)ss[1]; W = (int)ss[2]; }
    bool sh = (shifts[0] != 0u);
    int sx = sh ? 15 : 0, sy = sh ? 15 : 0, sz = sh ? 4 : 0;
    bool c64 = (g_coords64 != 0);

    int start = blockIdx.x * TILE;
    int end = start + TILE; if (end > n) end = n;
    for (int i = start + threadIdx.x; i < end; i += THREADS) {
        unsigned int b, zc, yc, xc;               // coords row = [b, z, y, x]
        if (c64) {
            const unsigned int* p = coords + (size_t)i * 8;
            b = p[0]; zc = p[2]; yc = p[4]; xc = p[6];
        } else {
            uint4 c = reinterpret_cast<const uint4*>(coords)[i];
            b = c.x; zc = c.y; yc = c.z; xc = c.w;
        }

        unsigned int x = (unsigned int)(((int)xc + sx) % W);
        unsigned int y = (unsigned int)(((int)yc + sy) % H);
        unsigned int z = (unsigned int)(((int)zc + sz) % D);

        unsigned int g0 = x & 0xFFu, g1 = y & 0xFFu, g2 = z & 0xFFu;

        // Axes -> transposed-gray (packed form of the reference bool algo).
        #pragma unroll
        for (int bit = 0; bit < 8; ++bit) {
            unsigned int low = (1u << (7 - bit)) - 1u;
            { unsigned int m = (g0 >> (7 - bit)) & 1u; if (m) g0 ^= low; }
            { unsigned int m = (g1 >> (7 - bit)) & 1u;
              if (m) g0 ^= low;
              else { unsigned int f = (g0 ^ g1) & low; g1 ^= f; g0 ^= f; } }
            { unsigned int m = (g2 >> (7 - bit)) & 1u;
              if (m) g0 ^= low;
              else { unsigned int f = (g0 ^ g2) & low; g2 ^= f; g0 ^= f; } }
        }

        unsigned int h = 0;
        #pragma unroll
        for (int bit = 7; bit >= 0; --bit) {
            h = (h << 3)
              | (((g0 >> bit) & 1u) << 2)
              | (((g1 >> bit) & 1u) << 1)
              |  ((g2 >> bit) & 1u);
        }
        h ^= h >> 16; h ^= h >> 8; h ^= h >> 4; h ^= h >> 2; h ^= h >> 1;

        unsigned int key = h | (b << 24);
        keys[i] = key;
        atomicAdd(&h1[key & 511u], 1u);
    }
    __syncthreads();
    for (int d = threadIdx.x; d < MAXBINS; d += THREADS)
        g_cnt[0][(size_t)d * ntiles + blockIdx.x] = h1[d];
}

// ---------------------------------------------------------------------------
// Block exclusive scan (256 threads, 8 warps). ws holds NWARP+1 uints.
// ---------------------------------------------------------------------------
__device__ __forceinline__ unsigned int block_exscan(unsigned int v,
                                                     unsigned int* ws,
                                                     unsigned int* total)
{
    int lane = threadIdx.x & 31, wid = threadIdx.x >> 5;
    unsigned int inc = v;
    #pragma unroll
    for (int o = 1; o < 32; o <<= 1) {
        unsigned int u = __shfl_up_sync(~0u, inc, o);
        if (lane >= o) inc += u;
    }
    __syncthreads();
    if (lane == 31) ws[wid] = inc;
    __syncthreads();
    if (threadIdx.x == 0) {
        unsigned int s = 0;
        #pragma unroll
        for (int i = 0; i < NWARP; ++i) { unsigned int t = ws[i]; ws[i] = s; s += t; }
        ws[NWARP] = s;
    }
    __syncthreads();
    if (total) *total = ws[NWARP];
    return inc - v + ws[wid];
}

// ---------------------------------------------------------------------------
// Scans: per-digit row scan over tiles, then digit-base scan.
// ---------------------------------------------------------------------------
__global__ void __launch_bounds__(THREADS)
scan_rows_kernel(unsigned int* __restrict__ counts,
                 unsigned int* __restrict__ rowtot, int nblocks)
{
    __shared__ unsigned int ws[NWARP + 1];
    unsigned int* row = counts + (size_t)blockIdx.x * nblocks;
    int base = threadIdx.x * 2;                   // 256*2 = 512 >= 489
    unsigned int v[2], s = 0;
    #pragma unroll
    for (int j = 0; j < 2; ++j) {
        int i = base + j;
        v[j] = (i < nblocks) ? row[i] : 0u;
        s += v[j];
    }
    unsigned int total;
    unsigned int run = block_exscan(s, ws, &total);
    #pragma unroll
    for (int j = 0; j < 2; ++j) {
        int i = base + j;
        if (i < nblocks) row[i] = run;
        run += v[j];
    }
    if (threadIdx.x == 0) rowtot[blockIdx.x] = total;
}

__global__ void __launch_bounds__(THREADS)
scan_base_kernel(const unsigned int* __restrict__ rowtot,
                 unsigned int* __restrict__ rowbase, int nbins)
{
    __shared__ unsigned int ws[NWARP + 1];
    int base = threadIdx.x * 2;
    unsigned int v[2], s = 0;
    #pragma unroll
    for (int j = 0; j < 2; ++j) {
        int i = base + j;
        v[j] = (i < nbins) ? rowtot[i] : 0u;
        s += v[j];
    }
    unsigned int run = block_exscan(s, ws, 0);
    #pragma unroll
    for (int j = 0; j < 2; ++j) {
        int i = base + j;
        if (i < nbins) rowbase[i] = run;
        run += v[j];
    }
}

// ---------------------------------------------------------------------------
// Stable scatter, single match pass. Fuses next-pass histogram via pos/TILE.
// FIRST=1: input plain keys, val = index. FINAL=1: output float(val).
// ---------------------------------------------------------------------------
template<int SHIFT, int BITS, int FIRST, int FINAL, int NSHIFT, int HASNEXT>
__global__ void __launch_bounds__(THREADS)
scatter_kernel(const unsigned int* __restrict__ keys_in,
               const uint2* __restrict__ pairs_in,
               uint2* __restrict__ pairs_out,
               float* __restrict__ outf,
               const unsigned int* __restrict__ counts,   // row-scanned
               const unsigned int* __restrict__ rowbase,
               unsigned int* __restrict__ counts_next,
               int n, int nblocks)
{
    const int NBINS = 1 << BITS;
    const int NNBINS_MASK = 511;                   // next digit mask (<=9 bits)
    __shared__ unsigned short cnt[NBINS][NWARP];   // [digit][warp]
    __shared__ unsigned int dpref[NBINS];
    __shared__ unsigned int gbase[NBINS];
    __shared__ unsigned int ws[NWARP + 1];

    int t = threadIdx.x, lane = t & 31, w = t >> 5;
    int start = blockIdx.x * TILE;

    unsigned int* cnt32 = (unsigned int*)&cnt[0][0];
    for (int i = t; i < NBINS * (NWARP / 2); i += THREADS) cnt32[i] = 0;
    for (int d = t; d < NBINS; d += THREADS)
        gbase[d] = counts[(size_t)d * nblocks + blockIdx.x] + rowbase[d];

    // Load (key,val), warp-blocked tile order (coalesced).
    unsigned int k[IPT], v[IPT];
    unsigned short r[IPT];
    bool act[IPT];
    #pragma unroll
    for (int q = 0; q < IPT; ++q) {
        int i = w * (32 * IPT) + q * 32 + lane;
        int g = start + i;
        act[q] = (g < n);
        if (act[q]) {
            if (FIRST) { k[q] = keys_in[g]; v[q] = (unsigned int)g; }
            else       { uint2 p = pairs_in[g]; k[q] = p.x; v[q] = p.y; }
        } else { k[q] = 0u; v[q] = 0u; }
    }
    __syncthreads();

    // Single match pass: count AND record within-warp stable rank r[q].
    #pragma unroll
    for (int q = 0; q < IPT; ++q) {
        unsigned int amask = __ballot_sync(~0u, act[q]);
        r[q] = 0;
        if (act[q]) {
            unsigned int d = (k[q] >> SHIFT) & (NBINS - 1);
            unsigned int peers = __match_any_sync(amask, d);
            int leader = __ffs(peers) - 1;
            unsigned int base = 0;
            if (lane == leader) {
                base = cnt[d][w];
                cnt[d][w] = (unsigned short)(base + __popc(peers));
            }
            base = __shfl_sync(peers, base, leader);
            r[q] = (unsigned short)(base + __popc(peers & ((1u << lane) - 1u)));
        }
    }
    __syncthreads();

    // Flat exclusive scan of cnt in (digit, warp) order.
    {
        unsigned short* flat = &cnt[0][0];
        const int E = (NBINS * NWARP) / THREADS;   // 16 (BITS=9) / 8 (BITS=8)
        unsigned int loc[16], s = 0;
        #pragma unroll
        for (int j = 0; j < E; ++j) { loc[j] = flat[t * E + j]; s += loc[j]; }
        unsigned int run = block_exscan(s, ws, 0);
        #pragma unroll
        for (int j = 0; j < E; ++j) {
            flat[t * E + j] = (unsigned short)run;
            run += loc[j];
        }
    }
    __syncthreads();
    for (int d = t; d < NBINS; d += THREADS) dpref[d] = cnt[d][0];
    __syncthreads();

    // Phase 2: pure arithmetic + store (+ fused next-pass histogram).
    #pragma unroll
    for (int q = 0; q < IPT; ++q) {
        if (act[q]) {
            unsigned int d = (k[q] >> SHIFT) & (NBINS - 1);
            unsigned int pos = gbase[d] + (unsigned int)cnt[d][w]
                             + (unsigned int)r[q] - dpref[d];
            if (FINAL) {
                outf[pos] = (float)v[q];
            } else {
                pairs_out[pos] = make_uint2(k[q], v[q]);
            }
            if (HASNEXT) {
                unsigned int dn = (k[q] >> NSHIFT) & NNBINS_MASK;
                atomicAdd(&counts_next[(size_t)dn * nblocks + (pos >> TILE_LOG)], 1u);
            }
        }
    }
}

// ---------------------------------------------------------------------------
// Host
// ---------------------------------------------------------------------------
extern "C" void kernel_launch(void* const* d_in, const int* in_sizes, int n_in,
                              void* d_out, int out_size)
{
    // Identify inputs by size signature.
    int ci = 0;
    for (int i = 1; i < n_in; ++i)
        if (in_sizes[i] > in_sizes[ci]) ci = i;
    int si = -1, hi = -1;
    for (int i = 0; i < n_in; ++i) {
        if (i == ci) continue;
        if (si < 0) { si = i; continue; }
        if (hi < 0) { hi = i; continue; }
    }
    if (hi >= 0 && in_sizes[hi] > in_sizes[si]) { int tq = si; si = hi; hi = tq; }
    if (si < 0) si = ci;
    if (hi < 0) hi = si;

    const unsigned int* coords = (const unsigned int*)d_in[ci];
    const unsigned int* ss     = (const unsigned int*)d_in[si];
    const unsigned int* shifts = (const unsigned int*)d_in[hi];

    int n = out_size;
    if (n > HS_MAXN) n = HS_MAXN;
    if (n <= 0) return;

    unsigned int *ka, *c0, *c1, *c2, *rowtot, *rowbase;
    uint2 *pa, *pb;
    cudaGetSymbolAddress((void**)&ka, g_keys);
    cudaGetSymbolAddress((void**)&pa, g_pairs_a);
    cudaGetSymbolAddress((void**)&pb, g_pairs_b);
    cudaGetSymbolAddress((void**)&c0, g_cnt);
    cudaGetSymbolAddress((void**)&rowtot, g_rowtot);
    cudaGetSymbolAddress((void**)&rowbase, g_rowbase);
    c1 = c0 + (size_t)MAXBINS * NBLK_MAX;
    c2 = c1 + (size_t)MAXBINS * NBLK_MAX;

    int ntiles = (n + TILE - 1) / TILE;

    detect_dtype_kernel<<<1, 256>>>(coords, 4096);
    hilbert_encode_kernel<<<ntiles, THREADS>>>(coords, ss, shifts, ka, n, ntiles);

    // Pass 1: bits [0,9), keys -> pairs_b; fused hist for pass 2 -> c1
    scan_rows_kernel<<<512, THREADS>>>(c0, rowtot, ntiles);
    scan_base_kernel<<<1, THREADS>>>(rowtot, rowbase, 512);
    scatter_kernel<0, 9, 1, 0, 9, 1><<<ntiles, THREADS>>>(
        ka, 0, pb, 0, c0, rowbase, c1, n, ntiles);

    // Pass 2: bits [9,18), pairs_b -> pairs_a; fused hist for pass 3 -> c2
    scan_rows_kernel<<<512, THREADS>>>(c1, rowtot, ntiles);
    scan_base_kernel<<<1, THREADS>>>(rowtot, rowbase, 512);
    scatter_kernel<9, 9, 0, 0, 18, 1><<<ntiles, THREADS>>>(
        0, pb, pa, 0, c1, rowbase, c2, n, ntiles);

    // Pass 3: bits [18,26), pairs_a -> float out
    scan_rows_kernel<<<256, THREADS>>>(c2, rowtot, ntiles);
    scan_base_kernel<<<1, THREADS>>>(rowtot, rowbase, 256);
    scatter_kernel<18, 8, 0, 1, 0, 0><<<ntiles, THREADS>>>(
        0, pa, 0, (float*)d_out, c2, rowbase, 0, n, ntiles);
}

// round 13
// speedup vs baseline: 2.2722x; 1.2454x over previous
#include <cuda_runtime.h>
#include <cuda_bf16.h>

// ---------------------------------------------------------------------------
// HilbertSerialization: 2M points -> 26-bit Hilbert+batch code -> stable argsort
// Output dtype: FLOAT32 (indices as float; all < 2^24, exact).
// 3-pass stable LSD radix sort (9,9,8 bits). Histograms FUSED into producers
// (encode -> pass1 tile counts + ALL-pass digit totals; scatter_p -> pass_{p+1}
// tile counts via pos/TILE atomics). One upfront scan computes all rowbases.
// 512-thread blocks for latency hiding. 9 launches. Zero allocations.
// ---------------------------------------------------------------------------

#define HS_MAXN   2000000
#define TILE      4096
#define TILE_LOG  12
#define THREADS   512
#define NWARP     (THREADS / 32)                  // 16
#define IPT       (TILE / THREADS)                // 8
#define MAXBINS   512
#define NBLK_MAX  ((HS_MAXN + TILE - 1) / TILE)   // 489

__device__ unsigned int g_keys[HS_MAXN];
__device__ uint2        g_pairs_a[HS_MAXN];
__device__ uint2        g_pairs_b[HS_MAXN];
__device__ unsigned int g_cnt[3][MAXBINS * NBLK_MAX];  // per-pass [digit][tile]
__device__ unsigned int g_hist[3][MAXBINS];            // per-pass digit totals
__device__ unsigned int g_rowbase[3][MAXBINS];         // exclusive digit bases
__device__ int g_coords64;

// ---------------------------------------------------------------------------
// detect: dtype sniff + zero the 3 global digit histograms.
// ---------------------------------------------------------------------------
__global__ void detect_dtype_kernel(const unsigned int* __restrict__ w, int nwords)
{
    __shared__ int ok;
    if (threadIdx.x == 0) ok = 1;
    __syncthreads();
    for (int i = 2 * threadIdx.x + 1; i < nwords; i += 2 * blockDim.x) {
        if (w[i] != 0u) { ok = 0; break; }
    }
    for (int i = threadIdx.x; i < 3 * MAXBINS; i += blockDim.x)
        ((unsigned int*)g_hist)[i] = 0u;
    __syncthreads();
    if (threadIdx.x == 0) g_coords64 = ok;
}

// ---------------------------------------------------------------------------
// encode: keys + pass-1 tile counts + digit totals for all 3 passes
//         + zero pass-2/3 tile counts.
// ---------------------------------------------------------------------------
__global__ void __launch_bounds__(THREADS)
hilbert_encode_kernel(const unsigned int* __restrict__ coords,
                      const unsigned int* __restrict__ ss,
                      const unsigned int* __restrict__ shifts,
                      unsigned int* __restrict__ keys,
                      int n, int ntiles)
{
    __shared__ unsigned int h1[MAXBINS], h2[MAXBINS], h3[MAXBINS];
    for (int i = threadIdx.x; i < MAXBINS; i += THREADS) {
        h1[i] = 0u; h2[i] = 0u; h3[i] = 0u;
    }
    // zero pass-2/3 tile counts (ordering before scatter atomics is by stream)
    {
        long long tot = 2LL * MAXBINS * ntiles;
        unsigned int* st = &g_cnt[1][0];
        for (long long i = (long long)blockIdx.x * THREADS + threadIdx.x;
             i < tot; i += (long long)gridDim.x * THREADS)
            st[i] = 0u;
    }
    __syncthreads();

    int D, H, W;                                  // sparse_shape = [D, H, W]
    if (ss[1] == 0u) { D = (int)ss[0]; H = (int)ss[2]; W = (int)ss[4]; }
    else             { D = (int)ss[0]; H = (int)ss[1]; W = (int)ss[2]; }
    bool sh = (shifts[0] != 0u);
    int sx = sh ? 15 : 0, sy = sh ? 15 : 0, sz = sh ? 4 : 0;
    bool c64 = (g_coords64 != 0);

    int start = blockIdx.x * TILE;
    int end = start + TILE; if (end > n) end = n;
    for (int i = start + threadIdx.x; i < end; i += THREADS) {
        unsigned int b, zc, yc, xc;               // coords row = [b, z, y, x]
        if (c64) {
            const unsigned int* p = coords + (size_t)i * 8;
            b = p[0]; zc = p[2]; yc = p[4]; xc = p[6];
        } else {
            uint4 c = reinterpret_cast<const uint4*>(coords)[i];
            b = c.x; zc = c.y; yc = c.z; xc = c.w;
        }

        unsigned int x = (unsigned int)(((int)xc + sx) % W);
        unsigned int y = (unsigned int)(((int)yc + sy) % H);
        unsigned int z = (unsigned int)(((int)zc + sz) % D);

        unsigned int g0 = x & 0xFFu, g1 = y & 0xFFu, g2 = z & 0xFFu;

        // Axes -> transposed-gray (packed form of the reference bool algo).
        #pragma unroll
        for (int bit = 0; bit < 8; ++bit) {
            unsigned int low = (1u << (7 - bit)) - 1u;
            { unsigned int m = (g0 >> (7 - bit)) & 1u; if (m) g0 ^= low; }
            { unsigned int m = (g1 >> (7 - bit)) & 1u;
              if (m) g0 ^= low;
              else { unsigned int f = (g0 ^ g1) & low; g1 ^= f; g0 ^= f; } }
            { unsigned int m = (g2 >> (7 - bit)) & 1u;
              if (m) g0 ^= low;
              else { unsigned int f = (g0 ^ g2) & low; g2 ^= f; g0 ^= f; } }
        }

        unsigned int h = 0;
        #pragma unroll
        for (int bit = 7; bit >= 0; --bit) {
            h = (h << 3)
              | (((g0 >> bit) & 1u) << 2)
              | (((g1 >> bit) & 1u) << 1)
              |  ((g2 >> bit) & 1u);
        }
        h ^= h >> 16; h ^= h >> 8; h ^= h >> 4; h ^= h >> 2; h ^= h >> 1;

        unsigned int key = h | (b << 24);
        keys[i] = key;
        atomicAdd(&h1[key & 511u], 1u);
        atomicAdd(&h2[(key >> 9) & 511u], 1u);
        atomicAdd(&h3[key >> 18], 1u);
    }
    __syncthreads();
    for (int d = threadIdx.x; d < MAXBINS; d += THREADS) {
        g_cnt[0][(size_t)d * ntiles + blockIdx.x] = h1[d];
        if (h1[d]) atomicAdd(&g_hist[0][d], h1[d]);
        if (h2[d]) atomicAdd(&g_hist[1][d], h2[d]);
        if (h3[d]) atomicAdd(&g_hist[2][d], h3[d]);
    }
}

// ---------------------------------------------------------------------------
// Block exclusive scan (THREADS threads, NWARP warps). ws holds NWARP+1 uints.
// ---------------------------------------------------------------------------
__device__ __forceinline__ unsigned int block_exscan(unsigned int v,
                                                     unsigned int* ws,
                                                     unsigned int* total)
{
    int lane = threadIdx.x & 31, wid = threadIdx.x >> 5;
    unsigned int inc = v;
    #pragma unroll
    for (int o = 1; o < 32; o <<= 1) {
        unsigned int u = __shfl_up_sync(~0u, inc, o);
        if (lane >= o) inc += u;
    }
    __syncthreads();
    if (lane == 31) ws[wid] = inc;
    __syncthreads();
    if (threadIdx.x == 0) {
        unsigned int s = 0;
        #pragma unroll
        for (int i = 0; i < NWARP; ++i) { unsigned int t = ws[i]; ws[i] = s; s += t; }
        ws[NWARP] = s;
    }
    __syncthreads();
    if (total) *total = ws[NWARP];
    return inc - v + ws[wid];
}

// ---------------------------------------------------------------------------
// scan_hist: one block; exclusive scan of all 3 digit-total histograms.
// ---------------------------------------------------------------------------
__global__ void __launch_bounds__(THREADS)
scan_hist_kernel()
{
    __shared__ unsigned int ws[NWARP + 1];
    for (int p = 0; p < 3; ++p) {
        unsigned int v = g_hist[p][threadIdx.x];
        unsigned int run = block_exscan(v, ws, 0);
        g_rowbase[p][threadIdx.x] = run;
        __syncthreads();
    }
}

// ---------------------------------------------------------------------------
// scan_rows: per-digit exclusive scan of tile counts (one block per digit).
// ---------------------------------------------------------------------------
__global__ void __launch_bounds__(THREADS)
scan_rows_kernel(unsigned int* __restrict__ counts, int nblocks)
{
    __shared__ unsigned int ws[NWARP + 1];
    unsigned int* row = counts + (size_t)blockIdx.x * nblocks;
    int i = threadIdx.x;                          // 512 >= 489
    unsigned int v = (i < nblocks) ? row[i] : 0u;
    unsigned int run = block_exscan(v, ws, 0);
    if (i < nblocks) row[i] = run;
}

// ---------------------------------------------------------------------------
// Stable scatter, single match pass. Fuses next-pass tile counts via pos/TILE.
// FIRST=1: input plain keys, val = index. FINAL=1: output float(val).
// ---------------------------------------------------------------------------
template<int SHIFT, int BITS, int FIRST, int FINAL, int NSHIFT, int HASNEXT, int PASS>
__global__ void __launch_bounds__(THREADS)
scatter_kernel(const unsigned int* __restrict__ keys_in,
               const uint2* __restrict__ pairs_in,
               uint2* __restrict__ pairs_out,
               float* __restrict__ outf,
               const unsigned int* __restrict__ counts,   // row-scanned
               unsigned int* __restrict__ counts_next,
               int n, int nblocks)
{
    const int NBINS = 1 << BITS;
    const int NNBINS_MASK = 511;                   // next digit mask (<=9 bits)
    __shared__ unsigned short cnt[NBINS][NWARP];   // [digit][warp]
    __shared__ unsigned int dpref[NBINS];
    __shared__ unsigned int gbase[NBINS];
    __shared__ unsigned int ws[NWARP + 1];

    int t = threadIdx.x, lane = t & 31, w = t >> 5;
    int start = blockIdx.x * TILE;

    unsigned int* cnt32 = (unsigned int*)&cnt[0][0];
    for (int i = t; i < NBINS * (NWARP / 2); i += THREADS) cnt32[i] = 0;
    for (int d = t; d < NBINS; d += THREADS)
        gbase[d] = counts[(size_t)d * nblocks + blockIdx.x] + g_rowbase[PASS][d];

    // Load (key,val), warp-blocked tile order (coalesced).
    unsigned int k[IPT], v[IPT];
    unsigned short r[IPT];
    bool act[IPT];
    #pragma unroll
    for (int q = 0; q < IPT; ++q) {
        int i = w * (32 * IPT) + q * 32 + lane;
        int g = start + i;
        act[q] = (g < n);
        if (act[q]) {
            if (FIRST) { k[q] = keys_in[g]; v[q] = (unsigned int)g; }
            else       { uint2 p = pairs_in[g]; k[q] = p.x; v[q] = p.y; }
        } else { k[q] = 0u; v[q] = 0u; }
    }
    __syncthreads();

    // Single match pass: count AND record within-warp stable rank r[q].
    #pragma unroll
    for (int q = 0; q < IPT; ++q) {
        unsigned int amask = __ballot_sync(~0u, act[q]);
        r[q] = 0;
        if (act[q]) {
            unsigned int d = (k[q] >> SHIFT) & (NBINS - 1);
            unsigned int peers = __match_any_sync(amask, d);
            int leader = __ffs(peers) - 1;
            unsigned int base = 0;
            if (lane == leader) {
                base = cnt[d][w];
                cnt[d][w] = (unsigned short)(base + __popc(peers));
            }
            base = __shfl_sync(peers, base, leader);
            r[q] = (unsigned short)(base + __popc(peers & ((1u << lane) - 1u)));
        }
    }
    __syncthreads();

    // Flat exclusive scan of cnt in (digit, warp) order.
    {
        unsigned short* flat = &cnt[0][0];
        const int E = (NBINS * NWARP) / THREADS;   // 16 (BITS=9) / 8 (BITS=8)
        unsigned int loc[16], s = 0;
        #pragma unroll
        for (int j = 0; j < E; ++j) { loc[j] = flat[t * E + j]; s += loc[j]; }
        unsigned int run = block_exscan(s, ws, 0);
        #pragma unroll
        for (int j = 0; j < E; ++j) {
            flat[t * E + j] = (unsigned short)run;
            run += loc[j];
        }
    }
    __syncthreads();
    for (int d = t; d < NBINS; d += THREADS) dpref[d] = cnt[d][0];
    __syncthreads();

    // Phase 2: pure arithmetic + store (+ fused next-pass tile counts).
    #pragma unroll
    for (int q = 0; q < IPT; ++q) {
        if (act[q]) {
            unsigned int d = (k[q] >> SHIFT) & (NBINS - 1);
            unsigned int pos = gbase[d] + (unsigned int)cnt[d][w]
                             + (unsigned int)r[q] - dpref[d];
            if (FINAL) {
                outf[pos] = (float)v[q];
            } else {
                pairs_out[pos] = make_uint2(k[q], v[q]);
            }
            if (HASNEXT) {
                unsigned int dn = (k[q] >> NSHIFT) & NNBINS_MASK;
                atomicAdd(&counts_next[(size_t)dn * nblocks + (pos >> TILE_LOG)], 1u);
            }
        }
    }
}

// ---------------------------------------------------------------------------
// Host
// ---------------------------------------------------------------------------
extern "C" void kernel_launch(void* const* d_in, const int* in_sizes, int n_in,
                              void* d_out, int out_size)
{
    // Identify inputs by size signature.
    int ci = 0;
    for (int i = 1; i < n_in; ++i)
        if (in_sizes[i] > in_sizes[ci]) ci = i;
    int si = -1, hi = -1;
    for (int i = 0; i < n_in; ++i) {
        if (i == ci) continue;
        if (si < 0) { si = i; continue; }
        if (hi < 0) { hi = i; continue; }
    }
    if (hi >= 0 && in_sizes[hi] > in_sizes[si]) { int tq = si; si = hi; hi = tq; }
    if (si < 0) si = ci;
    if (hi < 0) hi = si;

    const unsigned int* coords = (const unsigned int*)d_in[ci];
    const unsigned int* ss     = (const unsigned int*)d_in[si];
    const unsigned int* shifts = (const unsigned int*)d_in[hi];

    int n = out_size;
    if (n > HS_MAXN) n = HS_MAXN;
    if (n <= 0) return;

    unsigned int *ka, *c0, *c1, *c2;
    uint2 *pa, *pb;
    cudaGetSymbolAddress((void**)&ka, g_keys);
    cudaGetSymbolAddress((void**)&pa, g_pairs_a);
    cudaGetSymbolAddress((void**)&pb, g_pairs_b);
    cudaGetSymbolAddress((void**)&c0, g_cnt);
    c1 = c0 + (size_t)MAXBINS * NBLK_MAX;
    c2 = c1 + (size_t)MAXBINS * NBLK_MAX;

    int ntiles = (n + TILE - 1) / TILE;

    detect_dtype_kernel<<<1, 256>>>(coords, 4096);
    hilbert_encode_kernel<<<ntiles, THREADS>>>(coords, ss, shifts, ka, n, ntiles);
    scan_hist_kernel<<<1, THREADS>>>();

    // Pass 1: bits [0,9), keys -> pairs_b; fused tile counts for pass 2 -> c1
    scan_rows_kernel<<<512, THREADS>>>(c0, ntiles);
    scatter_kernel<0, 9, 1, 0, 9, 1, 0><<<ntiles, THREADS>>>(
        ka, 0, pb, 0, c0, c1, n, ntiles);

    // Pass 2: bits [9,18), pairs_b -> pairs_a; fused tile counts for pass 3 -> c2
    scan_rows_kernel<<<512, THREADS>>>(c1, ntiles);
    scatter_kernel<9, 9, 0, 0, 18, 1, 1><<<ntiles, THREADS>>>(
        0, pb, pa, 0, c1, c2, n, ntiles);

    // Pass 3: bits [18,26), pairs_a -> float out
    scan_rows_kernel<<<256, THREADS>>>(c2, ntiles);
    scatter_kernel<18, 8, 0, 1, 0, 0, 2><<<ntiles, THREADS>>>(
        0, pa, 0, (float*)d_out, c2, 0, n, ntiles);
}

// round 14
// speedup vs baseline: 2.3242x; 1.0229x over previous
#include <cuda_runtime.h>
#include <cuda_bf16.h>

// ---------------------------------------------------------------------------
// HilbertSerialization: 2M points -> 26-bit Hilbert+batch code -> stable argsort
// Output dtype: FLOAT32. 3-pass stable LSD radix sort (9,9,8 bits).
// Pass-2 output packed u32: (key bits[18,26) << 21) | val  (val < 2^21).
// Histograms fused into producers; one upfront digit-base scan; 512-thr blocks.
// 9 launches. All graph-capturable, zero allocations.
// ---------------------------------------------------------------------------

#define HS_MAXN   2000000
#define TILE      4096
#define TILE_LOG  12
#define THREADS   512
#define NWARP     (THREADS / 32)                  // 16
#define IPT       (TILE / THREADS)                // 8
#define MAXBINS   512
#define NBLK_MAX  ((HS_MAXN + TILE - 1) / TILE)   // 489
#define VAL_BITS  21
#define VAL_MASK  ((1u << VAL_BITS) - 1u)

__device__ unsigned int g_keys[HS_MAXN];
__device__ uint2        g_pairs[HS_MAXN];              // pass-1 output
__device__ unsigned int g_packed[HS_MAXN];             // pass-2 output
__device__ unsigned int g_cnt[3][MAXBINS * NBLK_MAX];  // per-pass [digit][tile]
__device__ unsigned int g_hist[3][MAXBINS];            // per-pass digit totals
__device__ unsigned int g_rowbase[3][MAXBINS];         // exclusive digit bases
__device__ int g_coords64;

// ---------------------------------------------------------------------------
__global__ void detect_dtype_kernel(const unsigned int* __restrict__ w, int nwords)
{
    __shared__ int ok;
    if (threadIdx.x == 0) ok = 1;
    __syncthreads();
    for (int i = 2 * threadIdx.x + 1; i < nwords; i += 2 * blockDim.x) {
        if (w[i] != 0u) { ok = 0; break; }
    }
    for (int i = threadIdx.x; i < 3 * MAXBINS; i += blockDim.x)
        ((unsigned int*)g_hist)[i] = 0u;
    __syncthreads();
    if (threadIdx.x == 0) g_coords64 = ok;
}

// Spread bits of an 8-bit value to every 3rd position (Morton).
__device__ __forceinline__ unsigned int spread3(unsigned int v)
{
    v = (v | (v << 16)) & 0x030000FFu;
    v = (v | (v << 8))  & 0x0300F00Fu;
    v = (v | (v << 4))  & 0x030C30C3u;
    v = (v | (v << 2))  & 0x09249249u;
    return v;
}

// ---------------------------------------------------------------------------
// encode: keys + pass-1 tile counts + digit totals for all 3 passes
//         + zero pass-2/3 tile counts.
// ---------------------------------------------------------------------------
__global__ void __launch_bounds__(THREADS)
hilbert_encode_kernel(const unsigned int* __restrict__ coords,
                      const unsigned int* __restrict__ ss,
                      const unsigned int* __restrict__ shifts,
                      unsigned int* __restrict__ keys,
                      int n, int ntiles)
{
    __shared__ unsigned int h1[MAXBINS], h2[MAXBINS], h3[MAXBINS];
    for (int i = threadIdx.x; i < MAXBINS; i += THREADS) {
        h1[i] = 0u; h2[i] = 0u; h3[i] = 0u;
    }
    {
        long long tot = 2LL * MAXBINS * ntiles;
        unsigned int* st = &g_cnt[1][0];
        for (long long i = (long long)blockIdx.x * THREADS + threadIdx.x;
             i < tot; i += (long long)gridDim.x * THREADS)
            st[i] = 0u;
    }
    __syncthreads();

    int D, H, W;                                  // sparse_shape = [D, H, W]
    if (ss[1] == 0u) { D = (int)ss[0]; H = (int)ss[2]; W = (int)ss[4]; }
    else             { D = (int)ss[0]; H = (int)ss[1]; W = (int)ss[2]; }
    bool sh = (shifts[0] != 0u);
    int sx = sh ? 15 : 0, sy = sh ? 15 : 0, sz = sh ? 4 : 0;
    bool c64 = (g_coords64 != 0);

    int start = blockIdx.x * TILE;
    int end = start + TILE; if (end > n) end = n;
    for (int i = start + threadIdx.x; i < end; i += THREADS) {
        unsigned int b, zc, yc, xc;               // coords row = [b, z, y, x]
        if (c64) {
            const unsigned int* p = coords + (size_t)i * 8;
            b = p[0]; zc = p[2]; yc = p[4]; xc = p[6];
        } else {
            uint4 c = reinterpret_cast<const uint4*>(coords)[i];
            b = c.x; zc = c.y; yc = c.z; xc = c.w;
        }

        unsigned int x = (unsigned int)(((int)xc + sx) % W);
        unsigned int y = (unsigned int)(((int)yc + sy) % H);
        unsigned int z = (unsigned int)(((int)zc + sz) % D);

        unsigned int g0 = x & 0xFFu, g1 = y & 0xFFu, g2 = z & 0xFFu;

        // Axes -> transposed-gray (packed form of the reference bool algo).
        #pragma unroll
        for (int bit = 0; bit < 8; ++bit) {
            unsigned int low = (1u << (7 - bit)) - 1u;
            { unsigned int m = (g0 >> (7 - bit)) & 1u; if (m) g0 ^= low; }
            { unsigned int m = (g1 >> (7 - bit)) & 1u;
              if (m) g0 ^= low;
              else { unsigned int f = (g0 ^ g1) & low; g1 ^= f; g0 ^= f; } }
            { unsigned int m = (g2 >> (7 - bit)) & 1u;
              if (m) g0 ^= low;
              else { unsigned int f = (g0 ^ g2) & low; g2 ^= f; g0 ^= f; } }
        }

        // Interleave via Morton spread: source bit b -> position 3b;
        // dim0 highest within each group (bit-major, dim-minor, MSB first).
        unsigned int h = (spread3(g0) << 2) | (spread3(g1) << 1) | spread3(g2);

        h ^= h >> 16; h ^= h >> 8; h ^= h >> 4; h ^= h >> 2; h ^= h >> 1;

        unsigned int key = h | (b << 24);
        keys[i] = key;
        atomicAdd(&h1[key & 511u], 1u);
        atomicAdd(&h2[(key >> 9) & 511u], 1u);
        atomicAdd(&h3[key >> 18], 1u);
    }
    __syncthreads();
    for (int d = threadIdx.x; d < MAXBINS; d += THREADS) {
        g_cnt[0][(size_t)d * ntiles + blockIdx.x] = h1[d];
        if (h1[d]) atomicAdd(&g_hist[0][d], h1[d]);
        if (h2[d]) atomicAdd(&g_hist[1][d], h2[d]);
        if (h3[d]) atomicAdd(&g_hist[2][d], h3[d]);
    }
}

// ---------------------------------------------------------------------------
__device__ __forceinline__ unsigned int block_exscan(unsigned int v,
                                                     unsigned int* ws,
                                                     unsigned int* total)
{
    int lane = threadIdx.x & 31, wid = threadIdx.x >> 5;
    unsigned int inc = v;
    #pragma unroll
    for (int o = 1; o < 32; o <<= 1) {
        unsigned int u = __shfl_up_sync(~0u, inc, o);
        if (lane >= o) inc += u;
    }
    __syncthreads();
    if (lane == 31) ws[wid] = inc;
    __syncthreads();
    if (threadIdx.x == 0) {
        unsigned int s = 0;
        #pragma unroll
        for (int i = 0; i < NWARP; ++i) { unsigned int t = ws[i]; ws[i] = s; s += t; }
        ws[NWARP] = s;
    }
    __syncthreads();
    if (total) *total = ws[NWARP];
    return inc - v + ws[wid];
}

__global__ void __launch_bounds__(THREADS)
scan_hist_kernel()
{
    __shared__ unsigned int ws[NWARP + 1];
    for (int p = 0; p < 3; ++p) {
        unsigned int v = g_hist[p][threadIdx.x];
        unsigned int run = block_exscan(v, ws, 0);
        g_rowbase[p][threadIdx.x] = run;
        __syncthreads();
    }
}

__global__ void __launch_bounds__(THREADS)
scan_rows_kernel(unsigned int* __restrict__ counts, int nblocks)
{
    __shared__ unsigned int ws[NWARP + 1];
    unsigned int* row = counts + (size_t)blockIdx.x * nblocks;
    int i = threadIdx.x;                          // 512 >= 489
    unsigned int v = (i < nblocks) ? row[i] : 0u;
    unsigned int run = block_exscan(v, ws, 0);
    if (i < nblocks) row[i] = run;
}

// ---------------------------------------------------------------------------
// Stable scatter, single match pass, uniform full-tile fast path.
// MODE 0: keys u32 in (val=index) -> uint2 out.        bits [0,9), fused c1.
// MODE 1: uint2 in -> packed u32 out (key8<<21 | val). bits [9,18), fused c2.
// MODE 2: packed u32 in -> float out.                  bits [18,26) (p >> 21).
// ---------------------------------------------------------------------------
template<int MODE>
__global__ void __launch_bounds__(THREADS)
scatter_kernel(const void* __restrict__ in_ptr,
               void* __restrict__ out_ptr,
               const unsigned int* __restrict__ counts,   // row-scanned
               unsigned int* __restrict__ counts_next,
               int n, int nblocks)
{
    const int SHIFT = (MODE == 0) ? 0 : (MODE == 1) ? 9 : VAL_BITS;
    const int BITS  = (MODE == 2) ? 8 : 9;
    const int NBINS = 1 << BITS;
    const int PASS  = MODE;
    __shared__ unsigned short cnt[NBINS][NWARP];   // [digit][warp]
    __shared__ unsigned int dpref[NBINS];
    __shared__ unsigned int gbase[NBINS];
    __shared__ unsigned int ws[NWARP + 1];

    int t = threadIdx.x, lane = t & 31, w = t >> 5;
    int start = blockIdx.x * TILE;
    bool full = (start + TILE <= n);               // block-uniform

    unsigned int* cnt32 = (unsigned int*)&cnt[0][0];
    for (int i = t; i < NBINS * (NWARP / 2); i += THREADS) cnt32[i] = 0;
    for (int d = t; d < NBINS; d += THREADS)
        gbase[d] = counts[(size_t)d * nblocks + blockIdx.x] + g_rowbase[PASS][d];

    // Load items, warp-blocked tile order (coalesced).
    unsigned int k[IPT], v[IPT];
    unsigned short r[IPT];
    bool act[IPT];
    #pragma unroll
    for (int q = 0; q < IPT; ++q) {
        int i = w * (32 * IPT) + q * 32 + lane;
        int g = start + i;
        act[q] = full || (g < n);
        if (act[q]) {
            if (MODE == 0) {
                k[q] = ((const unsigned int*)in_ptr)[g];
                v[q] = (unsigned int)g;
            } else if (MODE == 1) {
                uint2 p = ((const uint2*)in_ptr)[g];
                k[q] = p.x; v[q] = p.y;
            } else {
                unsigned int p = ((const unsigned int*)in_ptr)[g];
                k[q] = p; v[q] = p & VAL_MASK;
            }
        } else { k[q] = 0u; v[q] = 0u; }
    }
    __syncthreads();

    // Single match pass: count AND record within-warp stable rank r[q].
    #pragma unroll
    for (int q = 0; q < IPT; ++q) {
        unsigned int amask = full ? ~0u : __ballot_sync(~0u, act[q]);
        r[q] = 0;
        if (act[q]) {
            unsigned int d = (k[q] >> SHIFT) & (NBINS - 1);
            unsigned int peers = __match_any_sync(amask, d);
            int leader = __ffs(peers) - 1;
            unsigned int base = 0;
            if (lane == leader) {
                base = cnt[d][w];
                cnt[d][w] = (unsigned short)(base + __popc(peers));
            }
            base = __shfl_sync(peers, base, leader);
            r[q] = (unsigned short)(base + __popc(peers & ((1u << lane) - 1u)));
        }
    }
    __syncthreads();

    // Flat exclusive scan of cnt in (digit, warp) order.
    {
        unsigned short* flat = &cnt[0][0];
        const int E = (NBINS * NWARP) / THREADS;   // 16 (9-bit) / 8 (8-bit)
        unsigned int loc[16], s = 0;
        #pragma unroll
        for (int j = 0; j < E; ++j) { loc[j] = flat[t * E + j]; s += loc[j]; }
        unsigned int run = block_exscan(s, ws, 0);
        #pragma unroll
        for (int j = 0; j < E; ++j) {
            flat[t * E + j] = (unsigned short)run;
            run += loc[j];
        }
    }
    __syncthreads();
    for (int d = t; d < NBINS; d += THREADS) dpref[d] = cnt[d][0];
    __syncthreads();

    // Phase 2: pure arithmetic + store (+ fused next-pass tile counts).
    #pragma unroll
    for (int q = 0; q < IPT; ++q) {
        if (act[q]) {
            unsigned int d = (k[q] >> SHIFT) & (NBINS - 1);
            unsigned int pos = gbase[d] + (unsigned int)cnt[d][w]
                             + (unsigned int)r[q] - dpref[d];
            if (MODE == 0) {
                ((uint2*)out_ptr)[pos] = make_uint2(k[q], v[q]);
                unsigned int dn = (k[q] >> 9) & 511u;
                atomicAdd(&counts_next[(size_t)dn * nblocks + (pos >> TILE_LOG)], 1u);
            } else if (MODE == 1) {
                // pack: key bits [18,26) << 21 | val  (val < 2^21)
                ((unsigned int*)out_ptr)[pos] = ((k[q] >> 18) << VAL_BITS) | v[q];
                unsigned int dn = k[q] >> 18;
                atomicAdd(&counts_next[(size_t)dn * nblocks + (pos >> TILE_LOG)], 1u);
            } else {
                ((float*)out_ptr)[pos] = (float)v[q];
            }
        }
    }
}

// ---------------------------------------------------------------------------
// Host
// ---------------------------------------------------------------------------
extern "C" void kernel_launch(void* const* d_in, const int* in_sizes, int n_in,
                              void* d_out, int out_size)
{
    // Identify inputs by size signature.
    int ci = 0;
    for (int i = 1; i < n_in; ++i)
        if (in_sizes[i] > in_sizes[ci]) ci = i;
    int si = -1, hi = -1;
    for (int i = 0; i < n_in; ++i) {
        if (i == ci) continue;
        if (si < 0) { si = i; continue; }
        if (hi < 0) { hi = i; continue; }
    }
    if (hi >= 0 && in_sizes[hi] > in_sizes[si]) { int tq = si; si = hi; hi = tq; }
    if (si < 0) si = ci;
    if (hi < 0) hi = si;

    const unsigned int* coords = (const unsigned int*)d_in[ci];
    const unsigned int* ss     = (const unsigned int*)d_in[si];
    const unsigned int* shifts = (const unsigned int*)d_in[hi];

    int n = out_size;
    if (n > HS_MAXN) n = HS_MAXN;
    if (n <= 0) return;

    unsigned int *ka, *pk, *c0, *c1, *c2;
    uint2 *pp;
    cudaGetSymbolAddress((void**)&ka, g_keys);
    cudaGetSymbolAddress((void**)&pp, g_pairs);
    cudaGetSymbolAddress((void**)&pk, g_packed);
    cudaGetSymbolAddress((void**)&c0, g_cnt);
    c1 = c0 + (size_t)MAXBINS * NBLK_MAX;
    c2 = c1 + (size_t)MAXBINS * NBLK_MAX;

    int ntiles = (n + TILE - 1) / TILE;

    detect_dtype_kernel<<<1, 256>>>(coords, 4096);
    hilbert_encode_kernel<<<ntiles, THREADS>>>(coords, ss, shifts, ka, n, ntiles);
    scan_hist_kernel<<<1, THREADS>>>();

    // Pass 1: bits [0,9), keys -> pairs; fused tile counts for pass 2 -> c1
    scan_rows_kernel<<<512, THREADS>>>(c0, ntiles);
    scatter_kernel<0><<<ntiles, THREADS>>>(ka, pp, c0, c1, n, ntiles);

    // Pass 2: bits [9,18), pairs -> packed u32; fused counts for pass 3 -> c2
    scan_rows_kernel<<<512, THREADS>>>(c1, ntiles);
    scatter_kernel<1><<<ntiles, THREADS>>>(pp, pk, c1, c2, n, ntiles);

    // Pass 3: bits [18,26) via packed>>21, packed -> float out
    scan_rows_kernel<<<256, THREADS>>>(c2, ntiles);
    scatter_kernel<2><<<ntiles, THREADS>>>(pk, d_out, c2, 0, n, ntiles);
}